// round 9
// baseline (speedup 1.0000x reference)
#include <cuda_runtime.h>
#include <cuda_bf16.h>
#include <math.h>
#include <stdint.h>

// Problem constants
#define BB 512
#define LL 25
#define EE 300
#define EEP 320
#define HH 1024
#define DD 256
#define TT 128
#define BL (BB*LL)       // 12800
#define CATW (DD+HH)     // 1280

// ---------------- scratch (device globals; no allocation allowed) -----------
__device__ __nv_bfloat16 g_x_hi[BL*EEP], g_x_lo[BL*EEP];
__device__ float g_gi_all[BL*3*HH];
__device__ float g_enc_out[BL*HH];
__device__ float g_h[BB*HH];
__device__ __nv_bfloat16 g_h_hi[BB*HH], g_h_lo[BB*HH];
__device__ float g_gh[BB*3*HH];
__device__ __nv_bfloat16 g_cat_hi[BB*CATW], g_cat_lo[BB*CATW];
__device__ __nv_bfloat16 g_o_hi[BB*HH], g_o_lo[BB*HH];
__device__ float g_gi_dec[BB*3*HH];
__device__ int   g_inp[BB];
__device__ __nv_bfloat16 g_wencih_hi[3*HH*EEP], g_wencih_lo[3*HH*EEP];
__device__ __nv_bfloat16 g_wenchh_hi[3*HH*HH],  g_wenchh_lo[3*HH*HH];
__device__ __nv_bfloat16 g_wdecih_hi[3*HH*HH],  g_wdecih_lo[3*HH*HH];
__device__ __nv_bfloat16 g_wdechh_hi[3*HH*HH],  g_wdechh_lo[3*HH*HH];
__device__ __nv_bfloat16 g_wcomb_hi[HH*CATW],   g_wcomb_lo[HH*CATW];

__device__ __forceinline__ float sigmoidf_(float x) { return 1.f/(1.f+expf(-x)); }

__device__ __forceinline__ uint32_t smem_u32(const void* p) {
    uint32_t a;
    asm("{ .reg .u64 t; cvta.to.shared.u64 t, %1; cvt.u32.u64 %0, t; }" : "=r"(a) : "l"(p));
    return a;
}

#define LDM4(r, addr) \
    asm volatile("ldmatrix.sync.aligned.m8n8.x4.shared.b16 {%0,%1,%2,%3}, [%4];" \
        : "=r"((r)[0]), "=r"((r)[1]), "=r"((r)[2]), "=r"((r)[3]) : "r"(addr))

#define MMA16816(d, a, b) \
    asm volatile("mma.sync.aligned.m16n8k16.row.col.f32.bf16.bf16.f32 " \
        "{%0,%1,%2,%3}, {%4,%5,%6,%7}, {%8,%9}, {%0,%1,%2,%3};" \
        : "+f"((d)[0]), "+f"((d)[1]), "+f"((d)[2]), "+f"((d)[3]) \
        : "r"((a)[0]), "r"((a)[1]), "r"((a)[2]), "r"((a)[3]), "r"((b)[0]), "r"((b)[1]))

#define CPASYNC16(dst, src) \
    asm volatile("cp.async.cg.shared.global [%0], [%1], 16;" :: "r"(dst), "l"(src))

// ---------------- HMMA bf16 3-term split GEMM body ---------------------------
// C(M,N) = A(M,K)*B(N,K)^T, CTA tile 128(M)x64(N), BK=64, 256 threads
// (8 warps: 4m x 2n, 32x32 each). 2 CTAs/SM co-resident (96 KB smem each).
// Stage layout (48 KB): Ahi@0 (16K), Alo@16K, Bhi@32K (8K), Blo@40K.
enum { EPI_C=0, EPI_COMB=1 };
#define STG_SZ 49152

template<int EPI>
__device__ __forceinline__ void mma_body(
    char* sm, int bx, int by,
    const __nv_bfloat16* __restrict__ Ahi, const __nv_bfloat16* __restrict__ Alo, int lda,
    const __nv_bfloat16* __restrict__ Bhi, const __nv_bfloat16* __restrict__ Blo, int ldb,
    int K, float* __restrict__ Cf, int N,
    const float* __restrict__ bias, const float* __restrict__ bn,
    __nv_bfloat16* __restrict__ Ohi, __nv_bfloat16* __restrict__ Olo)
{
    const int tid  = threadIdx.x;
    const int lane = tid & 31, wid = tid >> 5;
    const int wm   = wid & 3;          // 4 warp-rows of 32
    const int wn   = wid >> 2;         // 2 warp-cols of 32
    const int m0   = by * 128, n0 = bx * 64;
    const uint32_t sbase = smem_u32(sm);

    // A staging: row sr (0..127), half sh -> 4 granules each of Ahi/Alo
    const int sr = tid >> 1, sh = tid & 1;
    // B staging: row srb (0..63), quarter sq -> 2 granules each of Bhi/Blo
    const int srb = tid >> 2, sq = tid & 3;
    const __nv_bfloat16* pa_hi = Ahi + (size_t)(m0 + sr) * lda;
    const __nv_bfloat16* pa_lo = Alo + (size_t)(m0 + sr) * lda;
    const __nv_bfloat16* pb_hi = Bhi + (size_t)(n0 + srb) * ldb;
    const __nv_bfloat16* pb_lo = Blo + (size_t)(n0 + srb) * ldb;
    const uint32_t swa = (uint32_t)(sr & 7);
    const uint32_t swb = (uint32_t)(srb & 7);

    auto stage = [&](int buf, int k0) {
        uint32_t dbase = sbase + (uint32_t)buf * STG_SZ;
        uint32_t da = dbase + (uint32_t)sr * 128u;
        #pragma unroll
        for (int c = 0; c < 4; c++) {
            uint32_t g = (uint32_t)(sh * 4 + c);
            uint32_t off = ((g ^ swa) << 4);
            CPASYNC16(da + off,          pa_hi + k0 + g * 8);
            CPASYNC16(da + 16384u + off, pa_lo + k0 + g * 8);
        }
        uint32_t db = dbase + 32768u + (uint32_t)srb * 128u;
        #pragma unroll
        for (int c = 0; c < 2; c++) {
            uint32_t g = (uint32_t)(sq * 2 + c);
            uint32_t off = ((g ^ swb) << 4);
            CPASYNC16(db + off,         pb_hi + k0 + g * 8);
            CPASYNC16(db + 8192u + off, pb_lo + k0 + g * 8);
        }
        asm volatile("cp.async.commit_group;" ::: "memory");
    };

    float acc[2][4][4];
    #pragma unroll
    for (int i = 0; i < 2; i++)
        #pragma unroll
        for (int j = 0; j < 4; j++)
            #pragma unroll
            for (int q = 0; q < 4; q++) acc[i][j][q] = 0.f;

    const int nt = K / 64;
    stage(0, 0);
    for (int it = 0; it < nt; it++) {
        if (it + 1 < nt) {
            stage((it + 1) & 1, (it + 1) * 64);
            asm volatile("cp.async.wait_group 1;" ::: "memory");
        } else {
            asm volatile("cp.async.wait_group 0;" ::: "memory");
        }
        __syncthreads();

        uint32_t tb = sbase + (uint32_t)(it & 1) * STG_SZ;
        #pragma unroll
        for (int ks = 0; ks < 4; ks++) {
            const int g0 = ks * 2;
            // A fragments (hi & lo), 2 m-tiles
            uint32_t ah[2][4], al[2][4];
            {
                int row_off = ((lane >> 3) & 1) * 8 + (lane & 7);
                int g = g0 + (lane >> 4);
                #pragma unroll
                for (int mt = 0; mt < 2; mt++) {
                    int row = wm * 32 + mt * 16 + row_off;
                    uint32_t addr = tb + (uint32_t)row * 128u
                                  + (uint32_t)((g ^ (row & 7)) << 4);
                    LDM4(ah[mt], addr);
                    LDM4(al[mt], addr + 16384u);
                }
            }
            // B fragments (hi & lo), 4 n-tiles via x4 loads
            uint32_t bh[4][2], bl[4][2];
            {
                int grp = lane >> 3;
                #pragma unroll
                for (int p = 0; p < 2; p++) {
                    int tile = 2 * p + (grp >> 1);
                    int g = g0 + (grp & 1);
                    int nrow = wn * 32 + tile * 8 + (lane & 7);
                    uint32_t addr = tb + 32768u + (uint32_t)nrow * 128u
                                  + (uint32_t)((g ^ (nrow & 7)) << 4);
                    uint32_t r4[4];
                    LDM4(r4, addr);
                    bh[2*p][0] = r4[0]; bh[2*p][1] = r4[1];
                    bh[2*p+1][0] = r4[2]; bh[2*p+1][1] = r4[3];
                    LDM4(r4, addr + 8192u);
                    bl[2*p][0] = r4[0]; bl[2*p][1] = r4[1];
                    bl[2*p+1][0] = r4[2]; bl[2*p+1][1] = r4[3];
                }
            }
            // term-major MMA ordering (8 independent per term)
            #pragma unroll
            for (int mt = 0; mt < 2; mt++)
                #pragma unroll
                for (int ntl = 0; ntl < 4; ntl++)
                    MMA16816(acc[mt][ntl], ah[mt], bh[ntl]);
            #pragma unroll
            for (int mt = 0; mt < 2; mt++)
                #pragma unroll
                for (int ntl = 0; ntl < 4; ntl++)
                    MMA16816(acc[mt][ntl], ah[mt], bl[ntl]);
            #pragma unroll
            for (int mt = 0; mt < 2; mt++)
                #pragma unroll
                for (int ntl = 0; ntl < 4; ntl++)
                    MMA16816(acc[mt][ntl], al[mt], bh[ntl]);
        }
        __syncthreads();
    }

    float s = 1.f, mu = 0.f, be = 0.f;
    if (EPI == EPI_COMB) { s = bn[0]*rsqrtf(bn[3]+1e-5f); mu = bn[2]; be = bn[1]; }
    #pragma unroll
    for (int mt = 0; mt < 2; mt++) {
        #pragma unroll
        for (int ntl = 0; ntl < 4; ntl++) {
            int row = m0 + wm*32 + mt*16 + (lane >> 2);
            int col = n0 + wn*32 + ntl*8 + (lane & 3)*2;
            if (EPI == EPI_C) {
                *(float2*)(Cf + (size_t)row*N + col) =
                    make_float2(acc[mt][ntl][0], acc[mt][ntl][1]);
                *(float2*)(Cf + (size_t)(row+8)*N + col) =
                    make_float2(acc[mt][ntl][2], acc[mt][ntl][3]);
            } else {
                #pragma unroll
                for (int q = 0; q < 4; q++) {
                    int r = row + (q >> 1)*8;
                    int c = col + (q & 1);
                    float v = acc[mt][ntl][q] + bias[c];
                    v = fmaxf((v - mu)*s + be, 0.f);
                    __nv_bfloat16 hv = __float2bfloat16(v);
                    Ohi[(size_t)r*HH + c] = hv;
                    Olo[(size_t)r*HH + c] = __float2bfloat16(v - __bfloat162float(hv));
                }
            }
        }
    }
}

__global__ __launch_bounds__(256, 2) void mma_gemm(
    const __nv_bfloat16* __restrict__ Ahi, const __nv_bfloat16* __restrict__ Alo, int lda,
    const __nv_bfloat16* __restrict__ Bhi, const __nv_bfloat16* __restrict__ Blo, int ldb,
    int K, float* __restrict__ Cf, int N)
{
    extern __shared__ char sm[];
    mma_body<EPI_C>(sm, blockIdx.x, blockIdx.y, Ahi, Alo, lda, Bhi, Blo, ldb,
                    K, Cf, N, nullptr, nullptr, nullptr, nullptr);
}

// merged decoder launch: z=0 -> gh = h @ dec_Whh^T (48x4); z=1 (x<16) -> comb -> split o
__global__ __launch_bounds__(256, 2) void comb_gh_kernel(
    const __nv_bfloat16* __restrict__ hhi, const __nv_bfloat16* __restrict__ hlo,
    const __nv_bfloat16* __restrict__ whh_hi, const __nv_bfloat16* __restrict__ whh_lo,
    float* __restrict__ gh,
    const __nv_bfloat16* __restrict__ chi, const __nv_bfloat16* __restrict__ clo,
    const __nv_bfloat16* __restrict__ wc_hi, const __nv_bfloat16* __restrict__ wc_lo,
    const float* __restrict__ comb_b, const float* __restrict__ bn2,
    __nv_bfloat16* __restrict__ ohi, __nv_bfloat16* __restrict__ olo)
{
    extern __shared__ char sm[];
    if (blockIdx.z == 0) {
        mma_body<EPI_C>(sm, blockIdx.x, blockIdx.y, hhi, hlo, HH, whh_hi, whh_lo, HH,
                        HH, gh, 3*HH, nullptr, nullptr, nullptr, nullptr);
    } else {
        if (blockIdx.x >= HH/64) return;
        mma_body<EPI_COMB>(sm, blockIdx.x, blockIdx.y, chi, clo, CATW, wc_hi, wc_lo, CATW,
                           CATW, nullptr, HH, comb_b, bn2, ohi, olo);
    }
}

// ---------------- weight splits ----------------------------------------------
__device__ __forceinline__ void split_seg(const float* src, __nv_bfloat16* hi,
                                          __nv_bfloat16* lo, int idx, int K, int Kpad)
{
    int r = idx / Kpad, k = idx - r*Kpad;
    float v = (k < K) ? src[(size_t)r*K + k] : 0.f;
    __nv_bfloat16 h = __float2bfloat16(v);
    hi[idx] = h;
    lo[idx] = __float2bfloat16(v - __bfloat162float(h));
}

__global__ void split_a_kernel(const float* __restrict__ w_eih, const float* __restrict__ w_ehh)
{
    int idx = blockIdx.x*blockDim.x + threadIdx.x;
    const int n0 = 3*HH*EEP, n1 = 3*HH*HH;
    if (idx < n0) split_seg(w_eih, g_wencih_hi, g_wencih_lo, idx, EE, EEP);
    else if (idx < n0 + n1) split_seg(w_ehh, g_wenchh_hi, g_wenchh_lo, idx - n0, HH, HH);
}

__global__ void split_b_kernel(const float* __restrict__ w_dih, const float* __restrict__ w_dhh,
                               const float* __restrict__ w_cmb)
{
    int idx = blockIdx.x*blockDim.x + threadIdx.x;
    const int n0 = 3*HH*HH, n1 = 3*HH*HH, n2 = HH*CATW;
    if (idx < n0) split_seg(w_dih, g_wdecih_hi, g_wdecih_lo, idx, HH, HH);
    else if (idx < n0+n1) split_seg(w_dhh, g_wdechh_hi, g_wdechh_lo, idx - n0, HH, HH);
    else if (idx < n0+n1+n2) split_seg(w_cmb, g_wcomb_hi, g_wcomb_lo, idx - n0 - n1, CATW, CATW);
}

// ---------------- small / fused kernels --------------------------------------
__global__ void init_kernel()
{
    int idx = blockIdx.x*blockDim.x + threadIdx.x;
    if (idx < BB*HH) {
        g_h[idx] = 0.f;
        g_h_hi[idx] = __float2bfloat16(0.f);
        g_h_lo[idx] = __float2bfloat16(0.f);
    }
    if (idx < BB) g_inp[idx] = TT;
}

__global__ void embed_renorm_kernel(const int* __restrict__ tokens,
                                    const float* __restrict__ w2v)
{
    int row = blockIdx.x;
    int tok = tokens[row];
    const float* src = w2v + (size_t)tok*EE;
    __shared__ float red[128];
    float ss = 0.f;
    for (int k = threadIdx.x; k < EE; k += blockDim.x) { float v = src[k]; ss += v*v; }
    red[threadIdx.x] = ss; __syncthreads();
    for (int s = blockDim.x>>1; s>0; s>>=1) {
        if (threadIdx.x < s) red[threadIdx.x] += red[threadIdx.x+s];
        __syncthreads();
    }
    float sc = fminf(1.f, 10.f/(sqrtf(red[0])+1e-7f));
    for (int k = threadIdx.x; k < EE; k += blockDim.x) {
        float v = src[k]*sc;
        __nv_bfloat16 h = __float2bfloat16(v);
        g_x_hi[(size_t)row*EEP + k] = h;
        g_x_lo[(size_t)row*EEP + k] = __float2bfloat16(v - __bfloat162float(h));
    }
    for (int k = EE + threadIdx.x; k < EEP; k += blockDim.x) {
        g_x_hi[(size_t)row*EEP + k] = __float2bfloat16(0.f);
        g_x_lo[(size_t)row*EEP + k] = __float2bfloat16(0.f);
    }
}

__global__ void gru_kernel(const float* __restrict__ gi0, int gi_stride,
                           const float* __restrict__ bih,
                           const float* __restrict__ gh0,
                           const float* __restrict__ bhh,
                           float* __restrict__ h,
                           float* __restrict__ outp, int out_stride)
{
    int idx = blockIdx.x*blockDim.x + threadIdx.x;
    if (idx >= BB*HH) return;
    int b = idx / HH, j = idx - b*HH;
    const float* p = gi0 + (size_t)b*gi_stride;
    float i_r = p[j], i_z = p[HH+j], i_n = p[2*HH+j];
    if (bih) { i_r += bih[j]; i_z += bih[HH+j]; i_n += bih[2*HH+j]; }
    const float* q = gh0 + (size_t)b*3*HH;
    float h_r = q[j]      + bhh[j];
    float h_z = q[HH+j]   + bhh[HH+j];
    float h_n = q[2*HH+j] + bhh[2*HH+j];
    float r = sigmoidf_(i_r + h_r);
    float z = sigmoidf_(i_z + h_z);
    float n = tanhf(i_n + r*h_n);
    float hn = (1.f - z)*n + z*h[idx];
    h[idx] = hn;
    __nv_bfloat16 hv = __float2bfloat16(hn);
    g_h_hi[idx] = hv;
    g_h_lo[idx] = __float2bfloat16(hn - __bfloat162float(hv));
    if (outp) outp[(size_t)b*out_stride + j] = hn;
}

// merged: [log_softmax+argmax of step lsm_t] then [embedding+attn+applied next step]
__global__ __launch_bounds__(256) void lsm_attn_kernel(
    const float* __restrict__ dec_emb,
    const float* __restrict__ attn_W, const float* __restrict__ attn_b,
    const float* __restrict__ Wt, const float* __restrict__ ob,
    const float* __restrict__ bn, float* __restrict__ out,
    int lsm_t, int do_attn)
{
    constexpr int CH = 64;
    __shared__ float sh[HH];
    __shared__ float Ws[TT][CH+1];
    __shared__ float red[256];
    __shared__ int   redi[128];
    __shared__ float semb[DD];
    __shared__ float saw[32];

    int b = blockIdx.x, tid = threadIdx.x;
    for (int k = tid; k < HH; k += 256) sh[k] = g_h[(size_t)b*HH + k];
    __syncthreads();

    int token;
    if (lsm_t >= 0) {
        int v = tid & 127, half = tid >> 7;
        float s = bn[0]*rsqrtf(bn[3]+1e-5f);
        float c0 = bn[1] - bn[2]*s;
        float acc = 0.f;
        for (int k0 = 0; k0 < HH; k0 += CH) {
            __syncthreads();
            for (int i = tid; i < TT*CH; i += 256) {
                int r = i >> 6, c = i & 63;
                Ws[r][c] = Wt[(size_t)r*HH + k0 + c];
            }
            __syncthreads();
            const int kb = half*32;
            #pragma unroll
            for (int k = 0; k < 32; k++)
                acc += (sh[k0 + kb + k]*s + c0) * Ws[v][kb + k];
        }
        __syncthreads();
        red[tid] = acc; __syncthreads();
        float x = 0.f;
        if (tid < 128) x = red[tid] + red[tid+128] + ob[tid];
        __syncthreads();
        if (tid < 128) { red[tid] = x; redi[tid] = tid; }
        __syncthreads();
        for (int st = 64; st > 0; st >>= 1) {
            if (tid < st) {
                if (red[tid+st] > red[tid]) { red[tid]=red[tid+st]; redi[tid]=redi[tid+st]; }
            }
            __syncthreads();
        }
        float m = red[0]; int am = redi[0];
        __syncthreads();
        red[tid] = (tid < 128) ? expf(x - m) : 0.f;
        __syncthreads();
        for (int st = 128; st > 0; st >>= 1) { if (tid<st) red[tid]+=red[tid+st]; __syncthreads(); }
        float lse = logf(red[0]);
        if (tid < 128) out[((size_t)b*LL + lsm_t)*TT + tid] = x - m - lse;
        token = am;
        __syncthreads();
    } else {
        token = g_inp[b];
    }

    if (!do_attn) return;

    float val = dec_emb[(size_t)token*DD + tid];
    red[tid] = val*val; __syncthreads();
    for (int s=128; s>0; s>>=1) { if (tid<s) red[tid]+=red[tid+s]; __syncthreads(); }
    float sc = fminf(1.f, 1.f/(sqrtf(red[0])+1e-7f));
    float e = val*sc;
    semb[tid] = e;
    {
        __nv_bfloat16 h = __float2bfloat16(e);
        g_cat_hi[(size_t)b*CATW + tid] = h;
        g_cat_lo[(size_t)b*CATW + tid] = __float2bfloat16(e - __bfloat162float(h));
    }
    __syncthreads();

    int warp = tid>>5, lane = tid&31;
    for (int l = warp; l < LL; l += 8) {
        const float* w = attn_W + (size_t)l*CATW;
        float acc = 0.f;
        for (int k = lane; k < DD; k += 32) acc += semb[k]*w[k];
        for (int k = lane; k < HH; k += 32) acc += sh[k]*w[DD+k];
        for (int o=16;o;o>>=1) acc += __shfl_xor_sync(0xffffffffu, acc, o);
        if (lane==0) saw[l] = acc + attn_b[l];
    }
    __syncthreads();
    if (warp==0) {
        float v = (lane<LL)? saw[lane] : -1e30f;
        float m = v;
        for (int o=16;o;o>>=1) m = fmaxf(m, __shfl_xor_sync(0xffffffffu, m, o));
        float ex = (lane<LL)? expf(v-m) : 0.f;
        float sm = ex;
        for (int o=16;o;o>>=1) sm += __shfl_xor_sync(0xffffffffu, sm, o);
        if (lane<LL) saw[lane] = ex/sm;
    }
    __syncthreads();

    const float* eo = g_enc_out + (size_t)b*LL*HH;
    for (int j = tid; j < HH; j += 256) {
        float acc = 0.f;
        #pragma unroll
        for (int l=0;l<LL;l++) acc += saw[l]*eo[(size_t)l*HH + j];
        __nv_bfloat16 h = __float2bfloat16(acc);
        g_cat_hi[(size_t)b*CATW + DD + j] = h;
        g_cat_lo[(size_t)b*CATW + DD + j] = __float2bfloat16(acc - __bfloat162float(h));
    }
}

// ---------------- launch ------------------------------------------------------
extern "C" void kernel_launch(void* const* d_in, const int* in_sizes, int n_in,
                              void* d_out, int out_size)
{
    const int*   tokens  = (const int*)  d_in[0];
    const float* w2v     = (const float*)d_in[1];
    const float* enc_Wih = (const float*)d_in[2];
    const float* enc_Whh = (const float*)d_in[3];
    const float* enc_bih = (const float*)d_in[4];
    const float* enc_bhh = (const float*)d_in[5];
    const float* dec_emb = (const float*)d_in[6];
    const float* attn_W  = (const float*)d_in[7];
    const float* attn_b  = (const float*)d_in[8];
    const float* comb_W  = (const float*)d_in[9];
    const float* comb_b  = (const float*)d_in[10];
    const float* dec_Wih = (const float*)d_in[11];
    const float* dec_Whh = (const float*)d_in[12];
    const float* dec_bih = (const float*)d_in[13];
    const float* dec_bhh = (const float*)d_in[14];
    const float* out_W   = (const float*)d_in[15];
    const float* out_b   = (const float*)d_in[16];
    const float* bn1     = (const float*)d_in[17];
    const float* bn2     = (const float*)d_in[18];
    float* out = (float*)d_out;

    __nv_bfloat16 *pxh, *pxl, *phh, *phl, *pch, *pcl, *poh, *pol;
    __nv_bfloat16 *pw_eih_h, *pw_eih_l, *pw_ehh_h, *pw_ehh_l;
    __nv_bfloat16 *pw_dih_h, *pw_dih_l, *pw_dhh_h, *pw_dhh_l, *pw_cmb_h, *pw_cmb_l;
    float *pgi_all, *penc_out, *ph, *pgh, *pgi_dec;
    cudaGetSymbolAddress((void**)&pxh, g_x_hi);       cudaGetSymbolAddress((void**)&pxl, g_x_lo);
    cudaGetSymbolAddress((void**)&phh, g_h_hi);       cudaGetSymbolAddress((void**)&phl, g_h_lo);
    cudaGetSymbolAddress((void**)&pch, g_cat_hi);     cudaGetSymbolAddress((void**)&pcl, g_cat_lo);
    cudaGetSymbolAddress((void**)&poh, g_o_hi);       cudaGetSymbolAddress((void**)&pol, g_o_lo);
    cudaGetSymbolAddress((void**)&pw_eih_h, g_wencih_hi); cudaGetSymbolAddress((void**)&pw_eih_l, g_wencih_lo);
    cudaGetSymbolAddress((void**)&pw_ehh_h, g_wenchh_hi); cudaGetSymbolAddress((void**)&pw_ehh_l, g_wenchh_lo);
    cudaGetSymbolAddress((void**)&pw_dih_h, g_wdecih_hi); cudaGetSymbolAddress((void**)&pw_dih_l, g_wdecih_lo);
    cudaGetSymbolAddress((void**)&pw_dhh_h, g_wdechh_hi); cudaGetSymbolAddress((void**)&pw_dhh_l, g_wdechh_lo);
    cudaGetSymbolAddress((void**)&pw_cmb_h, g_wcomb_hi);  cudaGetSymbolAddress((void**)&pw_cmb_l, g_wcomb_lo);
    cudaGetSymbolAddress((void**)&pgi_all,  g_gi_all);
    cudaGetSymbolAddress((void**)&penc_out, g_enc_out);
    cudaGetSymbolAddress((void**)&ph,       g_h);
    cudaGetSymbolAddress((void**)&pgh,      g_gh);
    cudaGetSymbolAddress((void**)&pgi_dec,  g_gi_dec);

    const int SMEM_MMA = 2 * STG_SZ;   // 96 KB -> 2 CTAs/SM
    cudaFuncSetAttribute(mma_gemm,       cudaFuncAttributeMaxDynamicSharedMemorySize, SMEM_MMA);
    cudaFuncSetAttribute(comb_gh_kernel, cudaFuncAttributeMaxDynamicSharedMemorySize, SMEM_MMA);

    const int EW = 2048;

    // launch order: index 3 = encoder recurrent GEMM (profiled slot)
    init_kernel<<<EW, 256>>>();                                           // 0
    split_a_kernel<<<(3*HH*EEP + 3*HH*HH + 255)/256, 256>>>(enc_Wih, enc_Whh);   // 1
    split_b_kernel<<<(2*3*HH*HH + HH*CATW + 255)/256, 256>>>(dec_Wih, dec_Whh, comb_W); // 2
    mma_gemm<<<dim3(3*HH/64, BB/128), 256, SMEM_MMA>>>(                   // 3 (profiled)
        phh, phl, HH, pw_ehh_h, pw_ehh_l, HH, HH, pgh, 3*HH);
    embed_renorm_kernel<<<BL, 128>>>(tokens, w2v);                        // 4
    mma_gemm<<<dim3(3*HH/64, BL/128), 256, SMEM_MMA>>>(                   // 5
        pxh, pxl, EEP, pw_eih_h, pw_eih_l, EEP, EEP, pgi_all, 3*HH);
    gru_kernel<<<EW, 256>>>(pgi_all, LL*3*HH, enc_bih,                    // 6 (t=0)
                            pgh, enc_bhh, ph, penc_out, LL*HH);

    // encoder recurrence t=1..24
    for (int t = 1; t < LL; t++) {
        mma_gemm<<<dim3(3*HH/64, BB/128), 256, SMEM_MMA>>>(
            phh, phl, HH, pw_ehh_h, pw_ehh_l, HH, HH, pgh, 3*HH);
        gru_kernel<<<EW, 256>>>(pgi_all + (size_t)t*3*HH, LL*3*HH, enc_bih,
                                pgh, enc_bhh, ph, penc_out + (size_t)t*HH, LL*HH);
    }

    // greedy attention decoder
    lsm_attn_kernel<<<BB, 256>>>(dec_emb, attn_W, attn_b, out_W, out_b, bn1, out, -1, 1);
    for (int t = 0; t < LL; t++) {
        comb_gh_kernel<<<dim3(3*HH/64, BB/128, 2), 256, SMEM_MMA>>>(
            phh, phl, pw_dhh_h, pw_dhh_l, pgh,
            pch, pcl, pw_cmb_h, pw_cmb_l, comb_b, bn2, poh, pol);
        mma_gemm<<<dim3(3*HH/64, BB/128), 256, SMEM_MMA>>>(
            poh, pol, HH, pw_dih_h, pw_dih_l, HH, HH, pgi_dec, 3*HH);
        gru_kernel<<<EW, 256>>>(pgi_dec, 3*HH, dec_bih, pgh, dec_bhh, ph, nullptr, 0);
        lsm_attn_kernel<<<BB, 256>>>(dec_emb, attn_W, attn_b, out_W, out_b, bn1, out,
                                     t, (t < LL-1) ? 1 : 0);
    }
}

// round 10
// speedup vs baseline: 1.0144x; 1.0144x over previous
#include <cuda_runtime.h>
#include <cuda_bf16.h>
#include <math.h>
#include <stdint.h>

// Problem constants
#define BB 512
#define LL 25
#define EE 300
#define EEP 320
#define HH 1024
#define DD 256
#define TT 128
#define BL (BB*LL)       // 12800
#define CATW (DD+HH)     // 1280

// ---------------- scratch (device globals; no allocation allowed) -----------
__device__ __nv_bfloat16 g_x_hi[BL*EEP], g_x_lo[BL*EEP];
__device__ float g_gi_all[BL*3*HH];
__device__ float g_enc_out[BL*HH];
__device__ float g_h[BB*HH];
__device__ __nv_bfloat16 g_h_hi[BB*HH], g_h_lo[BB*HH];
__device__ float g_gh[BB*3*HH];
__device__ __nv_bfloat16 g_cat_hi[BB*CATW], g_cat_lo[BB*CATW];
__device__ __nv_bfloat16 g_o_hi[BB*HH], g_o_lo[BB*HH];
__device__ float g_gi_dec[BB*3*HH];
__device__ int   g_inp[BB];
__device__ __nv_bfloat16 g_wencih_hi[3*HH*EEP], g_wencih_lo[3*HH*EEP];
__device__ __nv_bfloat16 g_wenchh_hi[3*HH*HH],  g_wenchh_lo[3*HH*HH];
__device__ __nv_bfloat16 g_wdecih_hi[3*HH*HH],  g_wdecih_lo[3*HH*HH];
__device__ __nv_bfloat16 g_wdechh_hi[3*HH*HH],  g_wdechh_lo[3*HH*HH];
__device__ __nv_bfloat16 g_wcomb_hi[HH*CATW],   g_wcomb_lo[HH*CATW];

__device__ __forceinline__ float sigmoidf_(float x) { return 1.f/(1.f+expf(-x)); }

__device__ __forceinline__ uint32_t smem_u32(const void* p) {
    uint32_t a;
    asm("{ .reg .u64 t; cvta.to.shared.u64 t, %1; cvt.u32.u64 %0, t; }" : "=r"(a) : "l"(p));
    return a;
}

#define LDM4(r, addr) \
    asm volatile("ldmatrix.sync.aligned.m8n8.x4.shared.b16 {%0,%1,%2,%3}, [%4];" \
        : "=r"((r)[0]), "=r"((r)[1]), "=r"((r)[2]), "=r"((r)[3]) : "r"(addr))

#define LDM2(r, addr) \
    asm volatile("ldmatrix.sync.aligned.m8n8.x2.shared.b16 {%0,%1}, [%2];" \
        : "=r"((r)[0]), "=r"((r)[1]) : "r"(addr))

#define MMA16816(d, a, b) \
    asm volatile("mma.sync.aligned.m16n8k16.row.col.f32.bf16.bf16.f32 " \
        "{%0,%1,%2,%3}, {%4,%5,%6,%7}, {%8,%9}, {%0,%1,%2,%3};" \
        : "+f"((d)[0]), "+f"((d)[1]), "+f"((d)[2]), "+f"((d)[3]) \
        : "r"((a)[0]), "r"((a)[1]), "r"((a)[2]), "r"((a)[3]), "r"((b)[0]), "r"((b)[1]))

#define CPASYNC16(dst, src) \
    asm volatile("cp.async.cg.shared.global [%0], [%1], 16;" :: "r"(dst), "l"(src))

// ---------------- HMMA bf16 3-term split GEMM body ---------------------------
// C(M,N) = A(M,K)*B(N,K)^T. CTA tile 128(M) x 32*NT(N), BK=64, 512 threads
// (16 warps: 4m x 4n; warp tile 32 x NT*8). NT=3 -> N_CTA=96; NT=4 -> 128.
// Stage: Ahi@0(16K) Alo@16K Bhi@32K(NR*128) Blo@32K+NR*128. Double buffered.
enum { EPI_C=0, EPI_COMB=1 };

template<int EPI, int NT>
__device__ __forceinline__ void mma_body(
    char* sm, int bx, int by,
    const __nv_bfloat16* __restrict__ Ahi, const __nv_bfloat16* __restrict__ Alo, int lda,
    const __nv_bfloat16* __restrict__ Bhi, const __nv_bfloat16* __restrict__ Blo, int ldb,
    int K, float* __restrict__ Cf, int N,
    const float* __restrict__ bias, const float* __restrict__ bn,
    __nv_bfloat16* __restrict__ Ohi, __nv_bfloat16* __restrict__ Olo)
{
    constexpr int WNT = NT * 8;        // warp N extent
    constexpr int NR  = 4 * WNT;       // CTA N extent (B rows staged)
    constexpr int BLO = NR * 128;      // Blo offset within B region
    constexpr int STG = 32768 + 2 * NR * 128;

    const int tid  = threadIdx.x;
    const int lane = tid & 31, wid = tid >> 5;
    const int wm   = wid & 3;          // 4 warp-rows of 32
    const int wn   = wid >> 2;         // 4 warp-cols of WNT
    const int m0   = by * 128, n0 = bx * NR;
    const uint32_t sbase = smem_u32(sm);

    // staging mapping: row = tid>>2, granule pair sq = tid&3
    const int sr = tid >> 2, sq = tid & 3;
    const __nv_bfloat16* pa_hi = Ahi + (size_t)(m0 + sr) * lda;
    const __nv_bfloat16* pa_lo = Alo + (size_t)(m0 + sr) * lda;
    const int rbq = (sr < NR) ? sr : (NR - 1);
    const __nv_bfloat16* pb_hi = Bhi + (size_t)(n0 + rbq) * ldb;
    const __nv_bfloat16* pb_lo = Blo + (size_t)(n0 + rbq) * ldb;
    const uint32_t swr = (uint32_t)(sr & 7);

    auto stage = [&](int buf, int k0) {
        uint32_t dbase = sbase + (uint32_t)buf * STG;
        uint32_t da = dbase + (uint32_t)sr * 128u;
        #pragma unroll
        for (int c = 0; c < 2; c++) {
            uint32_t g = (uint32_t)(sq * 2 + c);
            uint32_t off = ((g ^ swr) << 4);
            CPASYNC16(da + off,          pa_hi + k0 + g * 8);
            CPASYNC16(da + 16384u + off, pa_lo + k0 + g * 8);
        }
        if (sr < NR) {
            uint32_t db = dbase + 32768u + (uint32_t)sr * 128u;
            #pragma unroll
            for (int c = 0; c < 2; c++) {
                uint32_t g = (uint32_t)(sq * 2 + c);
                uint32_t off = ((g ^ swr) << 4);
                CPASYNC16(db + off,                 pb_hi + k0 + g * 8);
                CPASYNC16(db + (uint32_t)BLO + off, pb_lo + k0 + g * 8);
            }
        }
        asm volatile("cp.async.commit_group;" ::: "memory");
    };

    float acc[2][NT][4];
    #pragma unroll
    for (int i = 0; i < 2; i++)
        #pragma unroll
        for (int j = 0; j < NT; j++)
            #pragma unroll
            for (int q = 0; q < 4; q++) acc[i][j][q] = 0.f;

    const int nt = K / 64;
    stage(0, 0);
    for (int it = 0; it < nt; it++) {
        if (it + 1 < nt) {
            stage((it + 1) & 1, (it + 1) * 64);
            asm volatile("cp.async.wait_group 1;" ::: "memory");
        } else {
            asm volatile("cp.async.wait_group 0;" ::: "memory");
        }
        __syncthreads();

        uint32_t tb = sbase + (uint32_t)(it & 1) * STG;
        #pragma unroll
        for (int ks = 0; ks < 4; ks++) {
            const int g0 = ks * 2;
            // A fragments (hi & lo), 2 m-tiles
            uint32_t ah[2][4], al[2][4];
            {
                int row_off = ((lane >> 3) & 1) * 8 + (lane & 7);
                int g = g0 + (lane >> 4);
                #pragma unroll
                for (int mt = 0; mt < 2; mt++) {
                    int row = wm * 32 + mt * 16 + row_off;
                    uint32_t addr = tb + (uint32_t)row * 128u
                                  + (uint32_t)((g ^ (row & 7)) << 4);
                    LDM4(ah[mt], addr);
                    LDM4(al[mt], addr + 16384u);
                }
            }
            // B fragments (hi & lo), NT n-tiles
            uint32_t bh[NT][2], bl[NT][2];
            {
                int grp = lane >> 3;
                #pragma unroll
                for (int p = 0; p < NT/2; p++) {
                    int tile = 2 * p + (grp >> 1);
                    int g = g0 + (grp & 1);
                    int nrow = wn * WNT + tile * 8 + (lane & 7);
                    uint32_t addr = tb + 32768u + (uint32_t)nrow * 128u
                                  + (uint32_t)((g ^ (nrow & 7)) << 4);
                    uint32_t r4[4];
                    LDM4(r4, addr);
                    bh[2*p][0] = r4[0]; bh[2*p][1] = r4[1];
                    bh[2*p+1][0] = r4[2]; bh[2*p+1][1] = r4[3];
                    LDM4(r4, addr + BLO);
                    bl[2*p][0] = r4[0]; bl[2*p][1] = r4[1];
                    bl[2*p+1][0] = r4[2]; bl[2*p+1][1] = r4[3];
                }
                if (NT & 1) {
                    int tile = NT - 1;
                    int g = g0 + (grp & 1);
                    int nrow = wn * WNT + tile * 8 + (lane & 7);
                    uint32_t addr = tb + 32768u + (uint32_t)nrow * 128u
                                  + (uint32_t)((g ^ (nrow & 7)) << 4);
                    LDM2(bh[NT-1], addr);
                    LDM2(bl[NT-1], addr + BLO);
                }
            }
            // term-major MMA ordering
            #pragma unroll
            for (int mt = 0; mt < 2; mt++)
                #pragma unroll
                for (int ntl = 0; ntl < NT; ntl++)
                    MMA16816(acc[mt][ntl], ah[mt], bh[ntl]);
            #pragma unroll
            for (int mt = 0; mt < 2; mt++)
                #pragma unroll
                for (int ntl = 0; ntl < NT; ntl++)
                    MMA16816(acc[mt][ntl], ah[mt], bl[ntl]);
            #pragma unroll
            for (int mt = 0; mt < 2; mt++)
                #pragma unroll
                for (int ntl = 0; ntl < NT; ntl++)
                    MMA16816(acc[mt][ntl], al[mt], bh[ntl]);
        }
        __syncthreads();
    }

    float s = 1.f, mu = 0.f, be = 0.f;
    if (EPI == EPI_COMB) { s = bn[0]*rsqrtf(bn[3]+1e-5f); mu = bn[2]; be = bn[1]; }
    #pragma unroll
    for (int mt = 0; mt < 2; mt++) {
        #pragma unroll
        for (int ntl = 0; ntl < NT; ntl++) {
            int row = m0 + wm*32 + mt*16 + (lane >> 2);
            int col = n0 + wn*WNT + ntl*8 + (lane & 3)*2;
            if (EPI == EPI_C) {
                *(float2*)(Cf + (size_t)row*N + col) =
                    make_float2(acc[mt][ntl][0], acc[mt][ntl][1]);
                *(float2*)(Cf + (size_t)(row+8)*N + col) =
                    make_float2(acc[mt][ntl][2], acc[mt][ntl][3]);
            } else {
                #pragma unroll
                for (int q = 0; q < 4; q++) {
                    int r = row + (q >> 1)*8;
                    int c = col + (q & 1);
                    float v = acc[mt][ntl][q] + bias[c];
                    v = fmaxf((v - mu)*s + be, 0.f);
                    __nv_bfloat16 hv = __float2bfloat16(v);
                    Ohi[(size_t)r*HH + c] = hv;
                    Olo[(size_t)r*HH + c] = __float2bfloat16(v - __bfloat162float(hv));
                }
            }
        }
    }
}

// generic GEMM, NT=3 (CTA 128x96)
__global__ __launch_bounds__(512) void mma_gemm(
    const __nv_bfloat16* __restrict__ Ahi, const __nv_bfloat16* __restrict__ Alo, int lda,
    const __nv_bfloat16* __restrict__ Bhi, const __nv_bfloat16* __restrict__ Blo, int ldb,
    int K, float* __restrict__ Cf, int N)
{
    extern __shared__ char sm[];
    mma_body<EPI_C, 3>(sm, blockIdx.x, blockIdx.y, Ahi, Alo, lda, Bhi, Blo, ldb,
                       K, Cf, N, nullptr, nullptr, nullptr, nullptr);
}

// merged decoder launch: z=0 -> gh (NT=3, 32x4); z=1 (x<8) -> comb (NT=4) -> split o
__global__ __launch_bounds__(512) void comb_gh_kernel(
    const __nv_bfloat16* __restrict__ hhi, const __nv_bfloat16* __restrict__ hlo,
    const __nv_bfloat16* __restrict__ whh_hi, const __nv_bfloat16* __restrict__ whh_lo,
    float* __restrict__ gh,
    const __nv_bfloat16* __restrict__ chi, const __nv_bfloat16* __restrict__ clo,
    const __nv_bfloat16* __restrict__ wc_hi, const __nv_bfloat16* __restrict__ wc_lo,
    const float* __restrict__ comb_b, const float* __restrict__ bn2,
    __nv_bfloat16* __restrict__ ohi, __nv_bfloat16* __restrict__ olo)
{
    extern __shared__ char sm[];
    if (blockIdx.z == 0) {
        mma_body<EPI_C, 3>(sm, blockIdx.x, blockIdx.y, hhi, hlo, HH, whh_hi, whh_lo, HH,
                           HH, gh, 3*HH, nullptr, nullptr, nullptr, nullptr);
    } else {
        if (blockIdx.x >= HH/128) return;
        mma_body<EPI_COMB, 4>(sm, blockIdx.x, blockIdx.y, chi, clo, CATW, wc_hi, wc_lo, CATW,
                              CATW, nullptr, HH, comb_b, bn2, ohi, olo);
    }
}

// ---------------- weight splits ----------------------------------------------
__device__ __forceinline__ void split_seg(const float* src, __nv_bfloat16* hi,
                                          __nv_bfloat16* lo, int idx, int K, int Kpad)
{
    int r = idx / Kpad, k = idx - r*Kpad;
    float v = (k < K) ? src[(size_t)r*K + k] : 0.f;
    __nv_bfloat16 h = __float2bfloat16(v);
    hi[idx] = h;
    lo[idx] = __float2bfloat16(v - __bfloat162float(h));
}

__global__ void split_a_kernel(const float* __restrict__ w_eih, const float* __restrict__ w_ehh)
{
    int idx = blockIdx.x*blockDim.x + threadIdx.x;
    const int n0 = 3*HH*EEP, n1 = 3*HH*HH;
    if (idx < n0) split_seg(w_eih, g_wencih_hi, g_wencih_lo, idx, EE, EEP);
    else if (idx < n0 + n1) split_seg(w_ehh, g_wenchh_hi, g_wenchh_lo, idx - n0, HH, HH);
}

__global__ void split_b_kernel(const float* __restrict__ w_dih, const float* __restrict__ w_dhh,
                               const float* __restrict__ w_cmb)
{
    int idx = blockIdx.x*blockDim.x + threadIdx.x;
    const int n0 = 3*HH*HH, n1 = 3*HH*HH, n2 = HH*CATW;
    if (idx < n0) split_seg(w_dih, g_wdecih_hi, g_wdecih_lo, idx, HH, HH);
    else if (idx < n0+n1) split_seg(w_dhh, g_wdechh_hi, g_wdechh_lo, idx - n0, HH, HH);
    else if (idx < n0+n1+n2) split_seg(w_cmb, g_wcomb_hi, g_wcomb_lo, idx - n0 - n1, CATW, CATW);
}

// ---------------- small / fused kernels --------------------------------------
__global__ void init_kernel()
{
    int idx = blockIdx.x*blockDim.x + threadIdx.x;
    if (idx < BB*HH) {
        g_h[idx] = 0.f;
        g_h_hi[idx] = __float2bfloat16(0.f);
        g_h_lo[idx] = __float2bfloat16(0.f);
    }
    if (idx < BB) g_inp[idx] = TT;
}

__global__ void embed_renorm_kernel(const int* __restrict__ tokens,
                                    const float* __restrict__ w2v)
{
    int row = blockIdx.x;
    int tok = tokens[row];
    const float* src = w2v + (size_t)tok*EE;
    __shared__ float red[128];
    float ss = 0.f;
    for (int k = threadIdx.x; k < EE; k += blockDim.x) { float v = src[k]; ss += v*v; }
    red[threadIdx.x] = ss; __syncthreads();
    for (int s = blockDim.x>>1; s>0; s>>=1) {
        if (threadIdx.x < s) red[threadIdx.x] += red[threadIdx.x+s];
        __syncthreads();
    }
    float sc = fminf(1.f, 10.f/(sqrtf(red[0])+1e-7f));
    for (int k = threadIdx.x; k < EE; k += blockDim.x) {
        float v = src[k]*sc;
        __nv_bfloat16 h = __float2bfloat16(v);
        g_x_hi[(size_t)row*EEP + k] = h;
        g_x_lo[(size_t)row*EEP + k] = __float2bfloat16(v - __bfloat162float(h));
    }
    for (int k = EE + threadIdx.x; k < EEP; k += blockDim.x) {
        g_x_hi[(size_t)row*EEP + k] = __float2bfloat16(0.f);
        g_x_lo[(size_t)row*EEP + k] = __float2bfloat16(0.f);
    }
}

__global__ void gru_kernel(const float* __restrict__ gi0, int gi_stride,
                           const float* __restrict__ bih,
                           const float* __restrict__ gh0,
                           const float* __restrict__ bhh,
                           float* __restrict__ h,
                           float* __restrict__ outp, int out_stride)
{
    int idx = blockIdx.x*blockDim.x + threadIdx.x;
    if (idx >= BB*HH) return;
    int b = idx / HH, j = idx - b*HH;
    const float* p = gi0 + (size_t)b*gi_stride;
    float i_r = p[j], i_z = p[HH+j], i_n = p[2*HH+j];
    if (bih) { i_r += bih[j]; i_z += bih[HH+j]; i_n += bih[2*HH+j]; }
    const float* q = gh0 + (size_t)b*3*HH;
    float h_r = q[j]      + bhh[j];
    float h_z = q[HH+j]   + bhh[HH+j];
    float h_n = q[2*HH+j] + bhh[2*HH+j];
    float r = sigmoidf_(i_r + h_r);
    float z = sigmoidf_(i_z + h_z);
    float n = tanhf(i_n + r*h_n);
    float hn = (1.f - z)*n + z*h[idx];
    h[idx] = hn;
    __nv_bfloat16 hv = __float2bfloat16(hn);
    g_h_hi[idx] = hv;
    g_h_lo[idx] = __float2bfloat16(hn - __bfloat162float(hv));
    if (outp) outp[(size_t)b*out_stride + j] = hn;
}

// merged: [log_softmax+argmax of step lsm_t] then [embedding+attn+applied next step]
__global__ __launch_bounds__(256) void lsm_attn_kernel(
    const float* __restrict__ dec_emb,
    const float* __restrict__ attn_W, const float* __restrict__ attn_b,
    const float* __restrict__ Wt, const float* __restrict__ ob,
    const float* __restrict__ bn, float* __restrict__ out,
    int lsm_t, int do_attn)
{
    constexpr int CH = 64;
    __shared__ float sh[HH];
    __shared__ float Ws[TT][CH+1];
    __shared__ float red[256];
    __shared__ int   redi[128];
    __shared__ float semb[DD];
    __shared__ float saw[32];

    int b = blockIdx.x, tid = threadIdx.x;
    for (int k = tid; k < HH; k += 256) sh[k] = g_h[(size_t)b*HH + k];
    __syncthreads();

    int token;
    if (lsm_t >= 0) {
        int v = tid & 127, half = tid >> 7;
        float s = bn[0]*rsqrtf(bn[3]+1e-5f);
        float c0 = bn[1] - bn[2]*s;
        float acc = 0.f;
        for (int k0 = 0; k0 < HH; k0 += CH) {
            __syncthreads();
            for (int i = tid; i < TT*CH; i += 256) {
                int r = i >> 6, c = i & 63;
                Ws[r][c] = Wt[(size_t)r*HH + k0 + c];
            }
            __syncthreads();
            const int kb = half*32;
            #pragma unroll
            for (int k = 0; k < 32; k++)
                acc += (sh[k0 + kb + k]*s + c0) * Ws[v][kb + k];
        }
        __syncthreads();
        red[tid] = acc; __syncthreads();
        float x = 0.f;
        if (tid < 128) x = red[tid] + red[tid+128] + ob[tid];
        __syncthreads();
        if (tid < 128) { red[tid] = x; redi[tid] = tid; }
        __syncthreads();
        for (int st = 64; st > 0; st >>= 1) {
            if (tid < st) {
                if (red[tid+st] > red[tid]) { red[tid]=red[tid+st]; redi[tid]=redi[tid+st]; }
            }
            __syncthreads();
        }
        float m = red[0]; int am = redi[0];
        __syncthreads();
        red[tid] = (tid < 128) ? expf(x - m) : 0.f;
        __syncthreads();
        for (int st = 128; st > 0; st >>= 1) { if (tid<st) red[tid]+=red[tid+st]; __syncthreads(); }
        float lse = logf(red[0]);
        if (tid < 128) out[((size_t)b*LL + lsm_t)*TT + tid] = x - m - lse;
        token = am;
        __syncthreads();
    } else {
        token = g_inp[b];
    }

    if (!do_attn) return;

    float val = dec_emb[(size_t)token*DD + tid];
    red[tid] = val*val; __syncthreads();
    for (int s=128; s>0; s>>=1) { if (tid<s) red[tid]+=red[tid+s]; __syncthreads(); }
    float sc = fminf(1.f, 1.f/(sqrtf(red[0])+1e-7f));
    float e = val*sc;
    semb[tid] = e;
    {
        __nv_bfloat16 h = __float2bfloat16(e);
        g_cat_hi[(size_t)b*CATW + tid] = h;
        g_cat_lo[(size_t)b*CATW + tid] = __float2bfloat16(e - __bfloat162float(h));
    }
    __syncthreads();

    int warp = tid>>5, lane = tid&31;
    for (int l = warp; l < LL; l += 8) {
        const float* w = attn_W + (size_t)l*CATW;
        float acc = 0.f;
        for (int k = lane; k < DD; k += 32) acc += semb[k]*w[k];
        for (int k = lane; k < HH; k += 32) acc += sh[k]*w[DD+k];
        for (int o=16;o;o>>=1) acc += __shfl_xor_sync(0xffffffffu, acc, o);
        if (lane==0) saw[l] = acc + attn_b[l];
    }
    __syncthreads();
    if (warp==0) {
        float v = (lane<LL)? saw[lane] : -1e30f;
        float m = v;
        for (int o=16;o;o>>=1) m = fmaxf(m, __shfl_xor_sync(0xffffffffu, m, o));
        float ex = (lane<LL)? expf(v-m) : 0.f;
        float sm = ex;
        for (int o=16;o;o>>=1) sm += __shfl_xor_sync(0xffffffffu, sm, o);
        if (lane<LL) saw[lane] = ex/sm;
    }
    __syncthreads();

    const float* eo = g_enc_out + (size_t)b*LL*HH;
    for (int j = tid; j < HH; j += 256) {
        float acc = 0.f;
        #pragma unroll
        for (int l=0;l<LL;l++) acc += saw[l]*eo[(size_t)l*HH + j];
        __nv_bfloat16 h = __float2bfloat16(acc);
        g_cat_hi[(size_t)b*CATW + DD + j] = h;
        g_cat_lo[(size_t)b*CATW + DD + j] = __float2bfloat16(acc - __bfloat162float(h));
    }
}

// ---------------- launch ------------------------------------------------------
extern "C" void kernel_launch(void* const* d_in, const int* in_sizes, int n_in,
                              void* d_out, int out_size)
{
    const int*   tokens  = (const int*)  d_in[0];
    const float* w2v     = (const float*)d_in[1];
    const float* enc_Wih = (const float*)d_in[2];
    const float* enc_Whh = (const float*)d_in[3];
    const float* enc_bih = (const float*)d_in[4];
    const float* enc_bhh = (const float*)d_in[5];
    const float* dec_emb = (const float*)d_in[6];
    const float* attn_W  = (const float*)d_in[7];
    const float* attn_b  = (const float*)d_in[8];
    const float* comb_W  = (const float*)d_in[9];
    const float* comb_b  = (const float*)d_in[10];
    const float* dec_Wih = (const float*)d_in[11];
    const float* dec_Whh = (const float*)d_in[12];
    const float* dec_bih = (const float*)d_in[13];
    const float* dec_bhh = (const float*)d_in[14];
    const float* out_W   = (const float*)d_in[15];
    const float* out_b   = (const float*)d_in[16];
    const float* bn1     = (const float*)d_in[17];
    const float* bn2     = (const float*)d_in[18];
    float* out = (float*)d_out;

    __nv_bfloat16 *pxh, *pxl, *phh, *phl, *pch, *pcl, *poh, *pol;
    __nv_bfloat16 *pw_eih_h, *pw_eih_l, *pw_ehh_h, *pw_ehh_l;
    __nv_bfloat16 *pw_dih_h, *pw_dih_l, *pw_dhh_h, *pw_dhh_l, *pw_cmb_h, *pw_cmb_l;
    float *pgi_all, *penc_out, *ph, *pgh, *pgi_dec;
    cudaGetSymbolAddress((void**)&pxh, g_x_hi);       cudaGetSymbolAddress((void**)&pxl, g_x_lo);
    cudaGetSymbolAddress((void**)&phh, g_h_hi);       cudaGetSymbolAddress((void**)&phl, g_h_lo);
    cudaGetSymbolAddress((void**)&pch, g_cat_hi);     cudaGetSymbolAddress((void**)&pcl, g_cat_lo);
    cudaGetSymbolAddress((void**)&poh, g_o_hi);       cudaGetSymbolAddress((void**)&pol, g_o_lo);
    cudaGetSymbolAddress((void**)&pw_eih_h, g_wencih_hi); cudaGetSymbolAddress((void**)&pw_eih_l, g_wencih_lo);
    cudaGetSymbolAddress((void**)&pw_ehh_h, g_wenchh_hi); cudaGetSymbolAddress((void**)&pw_ehh_l, g_wenchh_lo);
    cudaGetSymbolAddress((void**)&pw_dih_h, g_wdecih_hi); cudaGetSymbolAddress((void**)&pw_dih_l, g_wdecih_lo);
    cudaGetSymbolAddress((void**)&pw_dhh_h, g_wdechh_hi); cudaGetSymbolAddress((void**)&pw_dhh_l, g_wdechh_lo);
    cudaGetSymbolAddress((void**)&pw_cmb_h, g_wcomb_hi);  cudaGetSymbolAddress((void**)&pw_cmb_l, g_wcomb_lo);
    cudaGetSymbolAddress((void**)&pgi_all,  g_gi_all);
    cudaGetSymbolAddress((void**)&penc_out, g_enc_out);
    cudaGetSymbolAddress((void**)&ph,       g_h);
    cudaGetSymbolAddress((void**)&pgh,      g_gh);
    cudaGetSymbolAddress((void**)&pgi_dec,  g_gi_dec);

    const int STG3 = 32768 + 2*96*128;     // 57344
    const int STG4 = 32768 + 2*128*128;    // 65536
    const int SMEM_G  = 2 * STG3;          // 114688
    const int SMEM_CG = 2 * STG4;          // 131072
    cudaFuncSetAttribute(mma_gemm,       cudaFuncAttributeMaxDynamicSharedMemorySize, SMEM_G);
    cudaFuncSetAttribute(comb_gh_kernel, cudaFuncAttributeMaxDynamicSharedMemorySize, SMEM_CG);

    const int EW = 2048;

    // launch order: index 3 = encoder recurrent GEMM (profiled slot)
    init_kernel<<<EW, 256>>>();                                           // 0
    split_a_kernel<<<(3*HH*EEP + 3*HH*HH + 255)/256, 256>>>(enc_Wih, enc_Whh);   // 1
    split_b_kernel<<<(2*3*HH*HH + HH*CATW + 255)/256, 256>>>(dec_Wih, dec_Whh, comb_W); // 2
    mma_gemm<<<dim3(3*HH/96, BB/128), 512, SMEM_G>>>(                     // 3 (profiled)
        phh, phl, HH, pw_ehh_h, pw_ehh_l, HH, HH, pgh, 3*HH);
    embed_renorm_kernel<<<BL, 128>>>(tokens, w2v);                        // 4
    mma_gemm<<<dim3(3*HH/96, BL/128), 512, SMEM_G>>>(                     // 5
        pxh, pxl, EEP, pw_eih_h, pw_eih_l, EEP, EEP, pgi_all, 3*HH);
    gru_kernel<<<EW, 256>>>(pgi_all, LL*3*HH, enc_bih,                    // 6 (t=0)
                            pgh, enc_bhh, ph, penc_out, LL*HH);

    // encoder recurrence t=1..24
    for (int t = 1; t < LL; t++) {
        mma_gemm<<<dim3(3*HH/96, BB/128), 512, SMEM_G>>>(
            phh, phl, HH, pw_ehh_h, pw_ehh_l, HH, HH, pgh, 3*HH);
        gru_kernel<<<EW, 256>>>(pgi_all + (size_t)t*3*HH, LL*3*HH, enc_bih,
                                pgh, enc_bhh, ph, penc_out + (size_t)t*HH, LL*HH);
    }

    // greedy attention decoder
    lsm_attn_kernel<<<BB, 256>>>(dec_emb, attn_W, attn_b, out_W, out_b, bn1, out, -1, 1);
    for (int t = 0; t < LL; t++) {
        comb_gh_kernel<<<dim3(3*HH/96, BB/128, 2), 512, SMEM_CG>>>(
            phh, phl, pw_dhh_h, pw_dhh_l, pgh,
            pch, pcl, pw_cmb_h, pw_cmb_l, comb_b, bn2, poh, pol);
        mma_gemm<<<dim3(3*HH/96, BB/128), 512, SMEM_G>>>(
            poh, pol, HH, pw_dih_h, pw_dih_l, HH, HH, pgi_dec, 3*HH);
        gru_kernel<<<EW, 256>>>(pgi_dec, 3*HH, dec_bih, pgh, dec_bhh, ph, nullptr, 0);
        lsm_attn_kernel<<<BB, 256>>>(dec_emb, attn_W, attn_b, out_W, out_b, bn1, out,
                                     t, (t < LL-1) ? 1 : 0);
    }
}